// round 10
// baseline (speedup 1.0000x reference)
#include <cuda_runtime.h>
#include <cuda_fp16.h>
#include <cstdint>
#include <math.h>

#define T_DIM 512
#define B_DIM 32
#define C1    512
#define H_DIM 512
#define M_DIM 2048          // 4 gates * H per direction
#define BC    (B_DIM * C1)  // 16384
#define NCHK  8
#define CHK   64            // T / NCHK

// ---------------------------------------------------------------------------
// Scratch (__device__ globals — no runtime allocation)
// ---------------------------------------------------------------------------
__device__ __align__(1024) __half g_gates[2ull * B_DIM * T_DIM * M_DIM];      // activated gates fp16
__device__ __align__(1024) __half g_xp[(size_t)(T_DIM + 2) * BC];             // padded x: rows 0..513
__device__ __align__(1024) __half g_h1p[(size_t)B_DIM * (T_DIM + 2) * 1024];  // layer-1 out, same padding
__device__ __align__(1024) __half g_wt1[2ull * 2 * M_DIM * C1];               // Wt[dir][kk][m][c]
__device__ __align__(1024) __half g_wt2[2ull * 2 * M_DIM * 2 * H_DIM];
__device__ float g_sumA[2 * B_DIM * NCHK * 512];
__device__ float g_sumB[2 * B_DIM * NCHK * 512];
__device__ float g_cst [2 * B_DIM * NCHK * 512];

// ---------------------------------------------------------------------------
__device__ __forceinline__ uint32_t smem_u32(const void* p) {
    uint32_t a;
    asm("{ .reg .u64 t; cvta.to.shared.u64 t, %1; cvt.u32.u64 %0, t; }" : "=r"(a) : "l"(p));
    return a;
}
__device__ __forceinline__ void cpa16(uint32_t dst, const void* src) {
    asm volatile("cp.async.cg.shared.global [%0], [%1], 16;" :: "r"(dst), "l"(src));
}
#define CP_COMMIT() asm volatile("cp.async.commit_group;" ::: "memory")
#define CP_WAIT1()  asm volatile("cp.async.wait_group 1;" ::: "memory")
#define CP_WAIT0()  asm volatile("cp.async.wait_group 0;" ::: "memory")

__device__ __forceinline__ void ldm_x4(uint32_t r[4], uint32_t addr) {
    asm volatile("ldmatrix.sync.aligned.m8n8.x4.shared.b16 {%0,%1,%2,%3}, [%4];"
                 : "=r"(r[0]), "=r"(r[1]), "=r"(r[2]), "=r"(r[3]) : "r"(addr));
}
__device__ __forceinline__ void mma_f16(float c[4], const uint32_t a[4], uint32_t b0, uint32_t b1) {
    asm volatile("mma.sync.aligned.m16n8k16.row.col.f32.f16.f16.f32 "
                 "{%0,%1,%2,%3}, {%4,%5,%6,%7}, {%8,%9}, {%0,%1,%2,%3};"
                 : "+f"(c[0]), "+f"(c[1]), "+f"(c[2]), "+f"(c[3])
                 : "r"(a[0]), "r"(a[1]), "r"(a[2]), "r"(a[3]), "r"(b0), "r"(b1));
}
__device__ __forceinline__ float sigm(float v) { return 1.f / (1.f + __expf(-v)); }

// ---------------------------------------------------------------------------
// Prepasses (pad-zeroing folded in so the GEMM is the 4th kernel launch)
// ---------------------------------------------------------------------------
__global__ void prep_w(const float* __restrict__ W, __half* __restrict__ Wt, int CIN,
                       __half* __restrict__ h1p_pads)
{
    int o = blockIdx.x * 256 + threadIdx.x;
    int c   = o % CIN;
    int m   = (o / CIN) & 2047;
    int kk  = (o / (CIN * 2048)) & 1;
    int dir = o / (CIN * 4096);
    int g = m >> 9, h = m & 511;
    Wt[o] = __float2half_rn(W[(((size_t)(dir * 4 + g) * 512 + h) * CIN + c) * 2 + kk]);
    if (h1p_pads && o < 32768) {
        __half z = __float2half_rn(0.f);
        int b = o >> 10, cc = o & 1023;
        h1p_pads[(size_t)b * (T_DIM + 2) * 1024 + cc] = z;
        h1p_pads[((size_t)b * (T_DIM + 2) + T_DIM + 1) * 1024 + cc] = z;
    }
}

__global__ void prep_x(const float* __restrict__ x, __half* __restrict__ Xp)
{
    int idx = blockIdx.x * 256 + threadIdx.x;
    int r = idx & (BC - 1);
    int t = idx >> 14;
    Xp[(size_t)(t + 1) * BC + r] = __float2half_rn(x[idx]);
    if (t == 0) {                       // zero pad rows 0 and T+1
        __half z = __float2half_rn(0.f);
        Xp[r] = z;
        Xp[(size_t)(T_DIM + 1) * BC + r] = z;
    }
}

// ---------------------------------------------------------------------------
// fp16 mma.sync m16n8k16 GEMM (R7 config: 128x128 CTA, 8 warps 32x64, 2 CTA/SM)
// + smem-staged coalesced epilogue (bias + activation -> 16B STG).
// dir=1 reads the padded buffer with negative row stride.
// ---------------------------------------------------------------------------
__global__ __launch_bounds__(256, 2)
void qrnn_gemm_mma(const __half* __restrict__ X,
                   const __half* __restrict__ Wt, const float* __restrict__ bias,
                   __half* __restrict__ G, int CIN, int row_stride, int b_stride)
{
    extern __shared__ __align__(128) char dsm[];   // 3 stages * 16 KB
    const int tid  = threadIdx.x;
    const int wid  = tid >> 5, lane = tid & 31;
    const int lm   = lane >> 2, lk = lane & 3;
    const int mo   = (wid & 3) * 32;
    const int no   = (wid >> 2) * 64;
    const int m0   = blockIdx.x * 128;
    const int bcol = blockIdx.y;
    const int b    = bcol >> 2, t0 = (bcol & 3) * 128;
    const int dir  = blockIdx.z;
    const int gate = blockIdx.x >> 2;
    const int CPK = CIN >> 5, NCH = CPK * 2;

    const uint32_t sbase = smem_u32(dsm);

    float acc[2][8][4];
    #pragma unroll
    for (int i = 0; i < 2; i++)
        #pragma unroll
        for (int j = 0; j < 8; j++)
            #pragma unroll
            for (int k = 0; k < 4; k++) acc[i][j][k] = 0.f;

    auto issue = [&](int ic, int s) {
        const int kk = (ic >= CPK) ? 1 : 0;
        const int c0 = (kk ? ic - CPK : ic) << 5;
        const __half* Ab = Wt + (size_t)((dir * 2 + kk) * 2048 + m0) * CIN + c0;
        const __half* Bb;
        ptrdiff_t rst;
        if (dir == 0) {
            Bb  = X + (size_t)b * b_stride + (size_t)(t0 + kk) * row_stride + c0;
            rst = row_stride;
        } else {
            Bb  = X + (size_t)b * b_stride + (size_t)(T_DIM + 1 - t0 - kk) * row_stride + c0;
            rst = -(ptrdiff_t)row_stride;
        }
        const uint32_t st = sbase + s * 16384;
        #pragma unroll
        for (int p = 0; p < 2; p++) {
            int gid = p * 256 + tid;               // 0..511 granules
            int r = gid >> 2, g = gid & 3;
            uint32_t off = (uint32_t)r * 64 + (uint32_t)((g ^ ((r >> 1) & 3)) << 4);
            cpa16(st + off,        Ab + (size_t)r * CIN + g * 8);
            cpa16(st + 8192 + off, Bb + (ptrdiff_t)r * rst + g * 8);
        }
    };

    issue(0, 0); CP_COMMIT();
    issue(1, 1); CP_COMMIT();

    const int lq = lane >> 3, lr = lane & 7;

    for (int ic = 0; ic < NCH; ic++) {
        const int s = ic % 3;
        CP_WAIT1();
        __syncthreads();

        const uint32_t As = sbase + s * 16384;
        const uint32_t Bs = As + 8192;
        #pragma unroll
        for (int ks = 0; ks < 2; ks++) {
            uint32_t a[2][4];
            #pragma unroll
            for (int mf = 0; mf < 2; mf++) {
                int R = mo + mf * 16 + lr + ((lq & 1) << 3);
                int g = ks * 2 + (lq >> 1);
                ldm_x4(a[mf], As + (uint32_t)R * 64 + (uint32_t)((g ^ ((R >> 1) & 3)) << 4));
            }
            uint32_t bf[4][4];
            #pragma unroll
            for (int nb = 0; nb < 4; nb++) {
                int R = no + nb * 16 + lr + ((lq >> 1) << 3);
                int g = ks * 2 + (lq & 1);
                ldm_x4(bf[nb], Bs + (uint32_t)R * 64 + (uint32_t)((g ^ ((R >> 1) & 3)) << 4));
            }
            #pragma unroll
            for (int mf = 0; mf < 2; mf++)
                #pragma unroll
                for (int nf = 0; nf < 8; nf++)
                    mma_f16(acc[mf][nf], a[mf], bf[nf >> 1][(nf & 1) * 2], bf[nf >> 1][(nf & 1) * 2 + 1]);
        }

        const int nx = ic + 2;
        if (nx < NCH) issue(nx, nx % 3);
        CP_COMMIT();
    }

    // --- epilogue: bias + activation -> swizzled smem tile -> coalesced STG
    CP_WAIT0();
    __syncthreads();          // all stages consumed; reuse smem as [128t x 128m] half tile

    const float* bb = bias + dir * 2048 + m0;
    #pragma unroll
    for (int mf = 0; mf < 2; mf++) {
        const int mr = mo + mf * 16 + lm;
        const float blo = bb[mr], bhi = bb[mr + 8];
        #pragma unroll
        for (int nf = 0; nf < 8; nf++) {
            const int t = no + nf * 8 + 2 * lk;
            float v0 = acc[mf][nf][0] + blo;
            float v1 = acc[mf][nf][1] + blo;
            float v2 = acc[mf][nf][2] + bhi;
            float v3 = acc[mf][nf][3] + bhi;
            if (gate == 0) {
                v0 = 2.f * sigm(2.f * v0) - 1.f;  v1 = 2.f * sigm(2.f * v1) - 1.f;
                v2 = 2.f * sigm(2.f * v2) - 1.f;  v3 = 2.f * sigm(2.f * v3) - 1.f;
            } else {
                v0 = sigm(v0); v1 = sigm(v1); v2 = sigm(v2); v3 = sigm(v3);
            }
            // swizzled tile write: byte = t*256 + ((m>>3 ^ (t>>1)&3)<<4) + (m&7)*2
            auto put = [&](int tt, int mm, float v) {
                uint32_t byte = (uint32_t)tt * 256 +
                                ((uint32_t)(((mm >> 3) ^ ((tt >> 1) & 3)) << 4)) +
                                ((uint32_t)(mm & 7) << 1);
                *(__half*)(dsm + byte) = __float2half_rn(v);
            };
            put(t,     mr,     v0);
            put(t + 1, mr,     v1);
            put(t,     mr + 8, v2);
            put(t + 1, mr + 8, v3);
        }
    }
    __syncthreads();

    __half* Gbase = G + ((size_t)(dir * B_DIM + b) * T_DIM + t0) * M_DIM + m0;
    #pragma unroll
    for (int i = 0; i < 8; i++) {
        int idx = i * 256 + tid;                 // 2048 chunks of 16B
        int row = idx >> 4, gm = idx & 15;
        uint4 v = *(const uint4*)(dsm + (uint32_t)row * 256 +
                                  ((uint32_t)((gm ^ ((row >> 1) & 3)) << 4)));
        *(uint4*)(Gbase + (size_t)row * M_DIM + gm * 8) = v;
    }
}

// ---------------------------------------------------------------------------
// Chunk-parallel scan (3 phases) — unchanged
// ---------------------------------------------------------------------------
__global__ void scan_a(const __half* __restrict__ G,
                       float* __restrict__ sA, float* __restrict__ sB)
{
    const int h = blockIdx.x * 128 + threadIdx.x;
    const int b = blockIdx.y;
    const int dir = blockIdx.z >> 3, ch = blockIdx.z & 7;
    const __half* Gd = G + ((size_t)(dir * B_DIM + b) * T_DIM + ch * CHK) * M_DIM + h;

    float a = 1.f, c = 0.f;
    #pragma unroll 4
    for (int t = 0; t < CHK; t++) {
        const __half* p = Gd + (size_t)t * M_DIM;
        float z = __half2float(p[0]);
        float f = __half2float(p[512]);
        float i = __half2float(p[1536]);
        a *= f;
        c = fmaf(f, c, i * z);
    }
    int o = (((dir * B_DIM + b) * NCHK) + ch) * 512 + h;
    sA[o] = a; sB[o] = c;
}

__global__ void scan_b(const float* __restrict__ sA, const float* __restrict__ sB,
                       float* __restrict__ cs)
{
    int idx = blockIdx.x * 256 + threadIdx.x;
    int lane = idx >> 9, h = idx & 511;
    float c = 0.f;
    #pragma unroll
    for (int j = 0; j < NCHK; j++) {
        int o = (lane * NCHK + j) * 512 + h;
        cs[o] = c;
        c = fmaf(sA[o], c, sB[o]);
    }
}

__global__ void scan_c(const __half* __restrict__ G, const float* __restrict__ cs,
                       float* __restrict__ o1f, __half* __restrict__ o1h,
                       float* __restrict__ hn, int mode)
{
    const int h = blockIdx.x * 128 + threadIdx.x;
    const int b = blockIdx.y;
    const int dir = blockIdx.z >> 3, ch = blockIdx.z & 7;
    const __half* Gd = G + ((size_t)(dir * B_DIM + b) * T_DIM + ch * CHK) * M_DIM + h;
    const int co = dir * 512 + h;

    float c = cs[(((dir * B_DIM + b) * NCHK) + ch) * 512 + h];
    #pragma unroll 4
    for (int t = 0; t < CHK; t++) {
        const __half* p = Gd + (size_t)t * M_DIM;
        float z  = __half2float(p[0]);
        float f  = __half2float(p[512]);
        float og = __half2float(p[1024]);
        float i  = __half2float(p[1536]);
        c = fmaf(f, c, i * z);
        float val = og * c;
        int gt = ch * CHK + t;
        if (mode == 0) {
            o1h[((size_t)b * (T_DIM + 2) + 1 + gt) * 1024 + co] = __float2half_rn(val);
        } else {
            o1f[((size_t)gt * B_DIM + b) * 1024 + co] = val;
        }
        if ((dir == 0 && gt == T_DIM - 2) || (dir == 1 && gt == 0))
            hn[(size_t)b * 1024 + co] = val;
    }
}

// ---------------------------------------------------------------------------
extern "C" void kernel_launch(void* const* d_in, const int* in_sizes, int n_in,
                              void* d_out, int out_size)
{
    const float* x  = (const float*)d_in[0];
    const float* w0 = (const float*)d_in[1];
    const float* b0 = (const float*)d_in[2];
    const float* w1 = (const float*)d_in[3];
    const float* b1 = (const float*)d_in[4];
    float* out = (float*)d_out;

    __half *gates, *xp, *h1p, *wt1, *wt2;
    float *sA, *sB, *cst;
    cudaGetSymbolAddress((void**)&gates, g_gates);
    cudaGetSymbolAddress((void**)&xp,  g_xp);
    cudaGetSymbolAddress((void**)&h1p, g_h1p);
    cudaGetSymbolAddress((void**)&wt1, g_wt1);
    cudaGetSymbolAddress((void**)&wt2, g_wt2);
    cudaGetSymbolAddress((void**)&sA,  g_sumA);
    cudaGetSymbolAddress((void**)&sB,  g_sumB);
    cudaGetSymbolAddress((void**)&cst, g_cst);

    cudaFuncSetAttribute(qrnn_gemm_mma, cudaFuncAttributeMaxDynamicSharedMemorySize, 48 * 1024);

    const size_t OUT_SEQ = (size_t)T_DIM * B_DIM * 2 * H_DIM;
    const size_t HN_L    = (size_t)B_DIM * 2 * H_DIM;

    // 3 prep launches, then the GEMM is launch #4 (ncu's profiled slot)
    prep_w<<<(2 * 2 * 2048 * C1) / 256, 256>>>(w0, wt1, C1, h1p);
    prep_w<<<(2 * 2 * 2048 * 2 * H_DIM) / 256, 256>>>(w1, wt2, 2 * H_DIM, nullptr);
    prep_x<<<(T_DIM * BC) / 256, 256>>>(x, xp);

    dim3 ggrid(16, 128, 2), gblk(256);
    dim3 scgrid(4, B_DIM, 16), scblk(128);
    const int DSM = 48 * 1024;

    // Layer 1: xp (row, b, c): row_stride = BC, b_stride = C1
    qrnn_gemm_mma<<<ggrid, gblk, DSM>>>(xp, wt1, b0, gates, C1, BC, C1);
    scan_a<<<scgrid, scblk>>>(gates, sA, sB);
    scan_b<<<128, 256>>>(sA, sB, cst);
    scan_c<<<scgrid, scblk>>>(gates, cst, nullptr, h1p, out + OUT_SEQ, 0);

    // Layer 2: h1p (b, row, c): row_stride = 1024, b_stride = 514*1024
    qrnn_gemm_mma<<<ggrid, gblk, DSM>>>(h1p, wt2, b1, gates, 2 * H_DIM,
                                        1024, (T_DIM + 2) * 1024);
    scan_a<<<scgrid, scblk>>>(gates, sA, sB);
    scan_b<<<128, 256>>>(sA, sB, cst);
    scan_c<<<scgrid, scblk>>>(gates, cst, out, nullptr, out + OUT_SEQ + HN_L, 1);
}

// round 11
// speedup vs baseline: 1.6818x; 1.6818x over previous
#include <cuda_runtime.h>
#include <cuda_fp16.h>
#include <cstdint>
#include <math.h>

#define T_DIM 512
#define B_DIM 32
#define C1    512
#define H_DIM 512
#define M_DIM 2048          // 4 gates * H per direction
#define BC    (B_DIM * C1)  // 16384
#define NCHK  8
#define CHK   64            // T / NCHK

// ---------------------------------------------------------------------------
// Scratch (__device__ globals — no runtime allocation)
// ---------------------------------------------------------------------------
__device__ __align__(1024) __half g_gates[2ull * B_DIM * T_DIM * M_DIM];      // activated gates fp16
__device__ __align__(1024) __half g_xp[(size_t)(T_DIM + 2) * BC];             // padded x: rows 0..513
__device__ __align__(1024) __half g_h1p[(size_t)B_DIM * (T_DIM + 2) * 1024];  // layer-1 out, same padding
__device__ __align__(1024) __half g_wt1[2ull * 2 * M_DIM * C1];               // Wt[dir][kk][m][c]
__device__ __align__(1024) __half g_wt2[2ull * 2 * M_DIM * 2 * H_DIM];
__device__ float g_sumA[2 * B_DIM * NCHK * 512];
__device__ float g_sumB[2 * B_DIM * NCHK * 512];
__device__ float g_cst [2 * B_DIM * NCHK * 512];

// ---------------------------------------------------------------------------
__device__ __forceinline__ uint32_t smem_u32(const void* p) {
    uint32_t a;
    asm("{ .reg .u64 t; cvta.to.shared.u64 t, %1; cvt.u32.u64 %0, t; }" : "=r"(a) : "l"(p));
    return a;
}
__device__ __forceinline__ void cpa16(uint32_t dst, const void* src) {
    asm volatile("cp.async.cg.shared.global [%0], [%1], 16;" :: "r"(dst), "l"(src));
}
#define CP_COMMIT() asm volatile("cp.async.commit_group;" ::: "memory")
#define CP_WAIT1()  asm volatile("cp.async.wait_group 1;" ::: "memory")

__device__ __forceinline__ void ldm_x4(uint32_t r[4], uint32_t addr) {
    asm volatile("ldmatrix.sync.aligned.m8n8.x4.shared.b16 {%0,%1,%2,%3}, [%4];"
                 : "=r"(r[0]), "=r"(r[1]), "=r"(r[2]), "=r"(r[3]) : "r"(addr));
}
__device__ __forceinline__ void mma_f16(float c[4], const uint32_t a[4], uint32_t b0, uint32_t b1) {
    asm volatile("mma.sync.aligned.m16n8k16.row.col.f32.f16.f16.f32 "
                 "{%0,%1,%2,%3}, {%4,%5,%6,%7}, {%8,%9}, {%0,%1,%2,%3};"
                 : "+f"(c[0]), "+f"(c[1]), "+f"(c[2]), "+f"(c[3])
                 : "r"(a[0]), "r"(a[1]), "r"(a[2]), "r"(a[3]), "r"(b0), "r"(b1));
}
__device__ __forceinline__ float sigm(float v) { return 1.f / (1.f + __expf(-v)); }

// ---------------------------------------------------------------------------
// Prepasses (pad-zeroing folded in so the GEMM is the 4th kernel launch)
// ---------------------------------------------------------------------------
__global__ void prep_w(const float* __restrict__ W, __half* __restrict__ Wt, int CIN,
                       __half* __restrict__ h1p_pads)
{
    int o = blockIdx.x * 256 + threadIdx.x;
    int c   = o % CIN;
    int m   = (o / CIN) & 2047;
    int kk  = (o / (CIN * 2048)) & 1;
    int dir = o / (CIN * 4096);
    int g = m >> 9, h = m & 511;
    Wt[o] = __float2half_rn(W[(((size_t)(dir * 4 + g) * 512 + h) * CIN + c) * 2 + kk]);
    if (h1p_pads && o < 32768) {
        __half z = __float2half_rn(0.f);
        int b = o >> 10, cc = o & 1023;
        h1p_pads[(size_t)b * (T_DIM + 2) * 1024 + cc] = z;
        h1p_pads[((size_t)b * (T_DIM + 2) + T_DIM + 1) * 1024 + cc] = z;
    }
}

__global__ void prep_x(const float* __restrict__ x, __half* __restrict__ Xp)
{
    int idx = blockIdx.x * 256 + threadIdx.x;
    int r = idx & (BC - 1);
    int t = idx >> 14;
    Xp[(size_t)(t + 1) * BC + r] = __float2half_rn(x[idx]);
    if (t == 0) {
        __half z = __float2half_rn(0.f);
        Xp[r] = z;
        Xp[(size_t)(T_DIM + 1) * BC + idx & (BC - 1)] = z;   // same r
    }
}

// ---------------------------------------------------------------------------
// fp16 mma.sync m16n8k16 GEMM. CTA 128m x 128t, 8 warps 32x64, 2 CTA/SM.
// K-chunk = 64 (stage A[128x64] 16KB + B[128x64] 16KB = 32KB; 3 stages 96KB).
// Swizzle: 128B rows of 8 granules, g ^= (r&7). ldmatrix addresses precomputed:
//   addr(ks) = addr0 XOR (ks<<5)   (k-step only flips offset bits 5-6).
// dir=1 reads the padded buffer with negative row stride.
// ---------------------------------------------------------------------------
__global__ __launch_bounds__(256, 2)
void qrnn_gemm_mma(const __half* __restrict__ X,
                   const __half* __restrict__ Wt, const float* __restrict__ bias,
                   __half* __restrict__ G, int CIN, int row_stride, int b_stride)
{
    extern __shared__ __align__(128) char dsm[];   // 3 stages * 32 KB
    const int tid  = threadIdx.x;
    const int wid  = tid >> 5, lane = tid & 31;
    const int lm   = lane >> 2, lk = lane & 3;
    const int mo   = (wid & 3) * 32;
    const int no   = (wid >> 2) * 64;
    const int m0   = blockIdx.x * 128;
    const int bcol = blockIdx.y;
    const int b    = bcol >> 2, t0 = (bcol & 3) * 128;
    const int dir  = blockIdx.z;
    const int gate = blockIdx.x >> 2;
    const int CPK = CIN >> 6, NCH = CPK * 2;       // 64-k chunks

    const uint32_t sbase = smem_u32(dsm);

    float acc[2][8][4];
    #pragma unroll
    for (int i = 0; i < 2; i++)
        #pragma unroll
        for (int j = 0; j < 8; j++)
            #pragma unroll
            for (int k = 0; k < 4; k++) acc[i][j][k] = 0.f;

    // --- async chunk loader: A = 1024 granules, B = 1024 granules (16B each)
    auto issue = [&](int ic, int s) {
        const int kk = (ic >= CPK) ? 1 : 0;
        const int c0 = (kk ? ic - CPK : ic) << 6;
        const __half* Ab = Wt + (size_t)((dir * 2 + kk) * 2048 + m0) * CIN + c0;
        const __half* Bb;
        ptrdiff_t rst;
        if (dir == 0) {
            Bb  = X + (size_t)b * b_stride + (size_t)(t0 + kk) * row_stride + c0;
            rst = row_stride;
        } else {
            Bb  = X + (size_t)b * b_stride + (size_t)(T_DIM + 1 - t0 - kk) * row_stride + c0;
            rst = -(ptrdiff_t)row_stride;
        }
        const uint32_t st = sbase + s * 32768;
        #pragma unroll
        for (int p = 0; p < 4; p++) {
            int gid = p * 256 + tid;               // 0..1023 granules
            int r = gid >> 3, g = gid & 7;
            uint32_t off = (uint32_t)r * 128 + (uint32_t)((g ^ (r & 7)) << 4);
            cpa16(st + off,         Ab + (size_t)r * CIN + g * 8);
            cpa16(st + 16384 + off, Bb + (ptrdiff_t)r * rst + g * 8);
        }
    };

    issue(0, 0); CP_COMMIT();
    issue(1, 1); CP_COMMIT();

    // --- precomputed fragment offsets (ks=0); per-ks address = base ^ (ks<<5)
    const int lq = lane >> 3, lr = lane & 7;
    uint32_t aoff[2], boff[4];
    #pragma unroll
    for (int mf = 0; mf < 2; mf++) {
        int R = mo + mf * 16 + lr + ((lq & 1) << 3);
        int q = lq >> 1;                            // granule bit0 for A
        aoff[mf] = (uint32_t)R * 128 + (uint32_t)((q ^ (R & 7)) << 4);
    }
    #pragma unroll
    for (int nb = 0; nb < 4; nb++) {
        int R = no + nb * 16 + lr + ((lq >> 1) << 3);
        int q = lq & 1;                             // granule bit0 for B
        boff[nb] = 16384u + (uint32_t)R * 128 + (uint32_t)((q ^ (R & 7)) << 4);
    }

    for (int ic = 0; ic < NCH; ic++) {
        const int s = ic % 3;
        CP_WAIT1();
        __syncthreads();

        const uint32_t St = sbase + s * 32768;
        #pragma unroll
        for (int ks = 0; ks < 4; ks++) {
            const uint32_t kx = (uint32_t)ks << 5;
            uint32_t a[2][4];
            #pragma unroll
            for (int mf = 0; mf < 2; mf++)
                ldm_x4(a[mf], (St + aoff[mf]) ^ kx);
            uint32_t bf[4][4];
            #pragma unroll
            for (int nb = 0; nb < 4; nb++)
                ldm_x4(bf[nb], (St + boff[nb]) ^ kx);
            #pragma unroll
            for (int mf = 0; mf < 2; mf++)
                #pragma unroll
                for (int nf = 0; nf < 8; nf++)
                    mma_f16(acc[mf][nf], a[mf], bf[nf >> 1][(nf & 1) * 2], bf[nf >> 1][(nf & 1) * 2 + 1]);
        }

        const int nx = ic + 2;
        if (nx < NCH) issue(nx, nx % 3);
        CP_COMMIT();
    }

    // --- epilogue (R7-proven): bias + activation, direct scattered stores
    const float* bb = bias + dir * 2048 + m0;
    __half* Gbase = G + ((size_t)(dir * B_DIM + b) * T_DIM + t0) * M_DIM + m0;
    #pragma unroll
    for (int mf = 0; mf < 2; mf++) {
        const int mr = mo + mf * 16 + lm;
        const float blo = bb[mr], bhi = bb[mr + 8];
        #pragma unroll
        for (int nf = 0; nf < 8; nf++) {
            const int t = no + nf * 8 + 2 * lk;
            __half* p = Gbase + (size_t)t * M_DIM + mr;
            float v0 = acc[mf][nf][0] + blo;
            float v1 = acc[mf][nf][1] + blo;
            float v2 = acc[mf][nf][2] + bhi;
            float v3 = acc[mf][nf][3] + bhi;
            if (gate == 0) {
                v0 = 2.f * sigm(2.f * v0) - 1.f;  v1 = 2.f * sigm(2.f * v1) - 1.f;
                v2 = 2.f * sigm(2.f * v2) - 1.f;  v3 = 2.f * sigm(2.f * v3) - 1.f;
            } else {
                v0 = sigm(v0); v1 = sigm(v1); v2 = sigm(v2); v3 = sigm(v3);
            }
            p[0] = __float2half_rn(v0);  p[M_DIM]     = __float2half_rn(v1);
            p[8] = __float2half_rn(v2);  p[M_DIM + 8] = __float2half_rn(v3);
        }
    }
}

// ---------------------------------------------------------------------------
// Chunk-parallel scan (3 phases) — unchanged
// ---------------------------------------------------------------------------
__global__ void scan_a(const __half* __restrict__ G,
                       float* __restrict__ sA, float* __restrict__ sB)
{
    const int h = blockIdx.x * 128 + threadIdx.x;
    const int b = blockIdx.y;
    const int dir = blockIdx.z >> 3, ch = blockIdx.z & 7;
    const __half* Gd = G + ((size_t)(dir * B_DIM + b) * T_DIM + ch * CHK) * M_DIM + h;

    float a = 1.f, c = 0.f;
    #pragma unroll 4
    for (int t = 0; t < CHK; t++) {
        const __half* p = Gd + (size_t)t * M_DIM;
        float z = __half2float(p[0]);
        float f = __half2float(p[512]);
        float i = __half2float(p[1536]);
        a *= f;
        c = fmaf(f, c, i * z);
    }
    int o = (((dir * B_DIM + b) * NCHK) + ch) * 512 + h;
    sA[o] = a; sB[o] = c;
}

__global__ void scan_b(const float* __restrict__ sA, const float* __restrict__ sB,
                       float* __restrict__ cs)
{
    int idx = blockIdx.x * 256 + threadIdx.x;
    int lane = idx >> 9, h = idx & 511;
    float c = 0.f;
    #pragma unroll
    for (int j = 0; j < NCHK; j++) {
        int o = (lane * NCHK + j) * 512 + h;
        cs[o] = c;
        c = fmaf(sA[o], c, sB[o]);
    }
}

__global__ void scan_c(const __half* __restrict__ G, const float* __restrict__ cs,
                       float* __restrict__ o1f, __half* __restrict__ o1h,
                       float* __restrict__ hn, int mode)
{
    const int h = blockIdx.x * 128 + threadIdx.x;
    const int b = blockIdx.y;
    const int dir = blockIdx.z >> 3, ch = blockIdx.z & 7;
    const __half* Gd = G + ((size_t)(dir * B_DIM + b) * T_DIM + ch * CHK) * M_DIM + h;
    const int co = dir * 512 + h;

    float c = cs[(((dir * B_DIM + b) * NCHK) + ch) * 512 + h];
    #pragma unroll 4
    for (int t = 0; t < CHK; t++) {
        const __half* p = Gd + (size_t)t * M_DIM;
        float z  = __half2float(p[0]);
        float f  = __half2float(p[512]);
        float og = __half2float(p[1024]);
        float i  = __half2float(p[1536]);
        c = fmaf(f, c, i * z);
        float val = og * c;
        int gt = ch * CHK + t;
        if (mode == 0) {
            o1h[((size_t)b * (T_DIM + 2) + 1 + gt) * 1024 + co] = __float2half_rn(val);
        } else {
            o1f[((size_t)gt * B_DIM + b) * 1024 + co] = val;
        }
        if ((dir == 0 && gt == T_DIM - 2) || (dir == 1 && gt == 0))
            hn[(size_t)b * 1024 + co] = val;
    }
}

// ---------------------------------------------------------------------------
extern "C" void kernel_launch(void* const* d_in, const int* in_sizes, int n_in,
                              void* d_out, int out_size)
{
    const float* x  = (const float*)d_in[0];
    const float* w0 = (const float*)d_in[1];
    const float* b0 = (const float*)d_in[2];
    const float* w1 = (const float*)d_in[3];
    const float* b1 = (const float*)d_in[4];
    float* out = (float*)d_out;

    __half *gates, *xp, *h1p, *wt1, *wt2;
    float *sA, *sB, *cst;
    cudaGetSymbolAddress((void**)&gates, g_gates);
    cudaGetSymbolAddress((void**)&xp,  g_xp);
    cudaGetSymbolAddress((void**)&h1p, g_h1p);
    cudaGetSymbolAddress((void**)&wt1, g_wt1);
    cudaGetSymbolAddress((void**)&wt2, g_wt2);
    cudaGetSymbolAddress((void**)&sA,  g_sumA);
    cudaGetSymbolAddress((void**)&sB,  g_sumB);
    cudaGetSymbolAddress((void**)&cst, g_cst);

    cudaFuncSetAttribute(qrnn_gemm_mma, cudaFuncAttributeMaxDynamicSharedMemorySize, 96 * 1024);

    const size_t OUT_SEQ = (size_t)T_DIM * B_DIM * 2 * H_DIM;
    const size_t HN_L    = (size_t)B_DIM * 2 * H_DIM;

    // 3 prep launches, then the GEMM is launch #4 (ncu's profiled slot)
    prep_w<<<(2 * 2 * 2048 * C1) / 256, 256>>>(w0, wt1, C1, h1p);
    prep_w<<<(2 * 2 * 2048 * 2 * H_DIM) / 256, 256>>>(w1, wt2, 2 * H_DIM, nullptr);
    prep_x<<<(T_DIM * BC) / 256, 256>>>(x, xp);

    dim3 ggrid(16, 128, 2), gblk(256);
    dim3 scgrid(4, B_DIM, 16), scblk(128);
    const int DSM = 96 * 1024;

    // Layer 1: xp (row, b, c): row_stride = BC, b_stride = C1
    qrnn_gemm_mma<<<ggrid, gblk, DSM>>>(xp, wt1, b0, gates, C1, BC, C1);
    scan_a<<<scgrid, scblk>>>(gates, sA, sB);
    scan_b<<<128, 256>>>(sA, sB, cst);
    scan_c<<<scgrid, scblk>>>(gates, cst, nullptr, h1p, out + OUT_SEQ, 0);

    // Layer 2: h1p (b, row, c): row_stride = 1024, b_stride = 514*1024
    qrnn_gemm_mma<<<ggrid, gblk, DSM>>>(h1p, wt2, b1, gates, 2 * H_DIM,
                                        1024, (T_DIM + 2) * 1024);
    scan_a<<<scgrid, scblk>>>(gates, sA, sB);
    scan_b<<<128, 256>>>(sA, sB, cst);
    scan_c<<<scgrid, scblk>>>(gates, cst, out, nullptr, out + OUT_SEQ + HN_L, 1);
}

// round 12
// speedup vs baseline: 1.7350x; 1.0317x over previous
#include <cuda_runtime.h>
#include <cuda_fp16.h>
#include <cstdint>
#include <math.h>

#define T_DIM 512
#define B_DIM 32
#define C1    512
#define H_DIM 512
#define M_DIM 2048          // 4 gates * H per direction
#define BC    (B_DIM * C1)  // 16384
#define NCHK  8
#define CHK   64            // T / NCHK

// ---------------------------------------------------------------------------
// Scratch (__device__ globals — no runtime allocation)
// ---------------------------------------------------------------------------
__device__ __align__(1024) __half g_gates[2ull * B_DIM * T_DIM * M_DIM];      // activated gates fp16
__device__ __align__(1024) __half g_xp[(size_t)(T_DIM + 2) * BC];             // padded x: rows 0..513
__device__ __align__(1024) __half g_h1p[(size_t)B_DIM * (T_DIM + 2) * 1024];  // layer-1 out, same padding
__device__ __align__(1024) __half g_wt1[2ull * 2 * M_DIM * C1];               // Wt[dir][kk][m][c]
__device__ __align__(1024) __half g_wt2[2ull * 2 * M_DIM * 2 * H_DIM];
__device__ float g_sumA[2 * B_DIM * NCHK * 512];
__device__ float g_sumB[2 * B_DIM * NCHK * 512];
__device__ float g_cst [2 * B_DIM * NCHK * 512];

// ---------------------------------------------------------------------------
__device__ __forceinline__ uint32_t smem_u32(const void* p) {
    uint32_t a;
    asm("{ .reg .u64 t; cvta.to.shared.u64 t, %1; cvt.u32.u64 %0, t; }" : "=r"(a) : "l"(p));
    return a;
}
__device__ __forceinline__ void cpa16(uint32_t dst, const void* src) {
    asm volatile("cp.async.cg.shared.global [%0], [%1], 16;" :: "r"(dst), "l"(src));
}
#define CP_COMMIT() asm volatile("cp.async.commit_group;" ::: "memory")
#define CP_WAIT1()  asm volatile("cp.async.wait_group 1;" ::: "memory")

__device__ __forceinline__ void ldm_x4(uint32_t r[4], uint32_t addr) {
    asm volatile("ldmatrix.sync.aligned.m8n8.x4.shared.b16 {%0,%1,%2,%3}, [%4];"
                 : "=r"(r[0]), "=r"(r[1]), "=r"(r[2]), "=r"(r[3]) : "r"(addr));
}
__device__ __forceinline__ void mma_f16(float c[4], const uint32_t a[4], uint32_t b0, uint32_t b1) {
    asm volatile("mma.sync.aligned.m16n8k16.row.col.f32.f16.f16.f32 "
                 "{%0,%1,%2,%3}, {%4,%5,%6,%7}, {%8,%9}, {%0,%1,%2,%3};"
                 : "+f"(c[0]), "+f"(c[1]), "+f"(c[2]), "+f"(c[3])
                 : "r"(a[0]), "r"(a[1]), "r"(a[2]), "r"(a[3]), "r"(b0), "r"(b1));
}
__device__ __forceinline__ float sigm(float v) { return 1.f / (1.f + __expf(-v)); }

// ---------------------------------------------------------------------------
// Prepasses
// ---------------------------------------------------------------------------
__global__ void prep_w(const float* __restrict__ W, __half* __restrict__ Wt, int CIN,
                       __half* __restrict__ h1p_pads)
{
    int o = blockIdx.x * 256 + threadIdx.x;
    int c   = o % CIN;
    int m   = (o / CIN) & 2047;
    int kk  = (o / (CIN * 2048)) & 1;
    int dir = o / (CIN * 4096);
    int g = m >> 9, h = m & 511;
    Wt[o] = __float2half_rn(W[(((size_t)(dir * 4 + g) * 512 + h) * CIN + c) * 2 + kk]);
    if (h1p_pads && o < 32768) {
        __half z = __float2half_rn(0.f);
        int b = o >> 10, cc = o & 1023;
        h1p_pads[(size_t)b * (T_DIM + 2) * 1024 + cc] = z;
        h1p_pads[((size_t)b * (T_DIM + 2) + T_DIM + 1) * 1024 + cc] = z;
    }
}

__global__ void prep_x(const float* __restrict__ x, __half* __restrict__ Xp)
{
    int idx = blockIdx.x * 256 + threadIdx.x;
    int r = idx & (BC - 1);
    int t = idx >> 14;
    Xp[(size_t)(t + 1) * BC + r] = __float2half_rn(x[idx]);
    if (t == 0) {
        __half z = __float2half_rn(0.f);
        Xp[r] = z;
        Xp[(size_t)(T_DIM + 1) * BC + r] = z;
    }
}

// ---------------------------------------------------------------------------
// fp16 mma.sync m16n8k16 GEMM. CTA 128m x 128t, 4 warps of 64x64, 2 CTA/SM.
// K-chunk = 64 (stage A[128x64] 16KB + B[128x64] 16KB = 32KB; 3 stages 96KB).
// Swizzle: 128B rows of 8 granules, g ^= (r&7). ldmatrix addr(ks) = addr0 ^ (ks<<5).
// Loader smem/global offsets precomputed in registers (chunk-invariant).
// dir=1 reads the padded buffer with negative row stride.
// ---------------------------------------------------------------------------
__global__ __launch_bounds__(128, 2)
void qrnn_gemm_mma(const __half* __restrict__ X,
                   const __half* __restrict__ Wt, const float* __restrict__ bias,
                   __half* __restrict__ G, int CIN, int row_stride, int b_stride)
{
    extern __shared__ __align__(128) char dsm[];   // 3 stages * 32 KB
    const int tid  = threadIdx.x;
    const int wid  = tid >> 5, lane = tid & 31;
    const int lm   = lane >> 2, lk = lane & 3;
    const int mo   = (wid & 1) * 64;               // 2 m-warps
    const int no   = (wid >> 1) * 64;              // 2 t-warps
    const int m0   = blockIdx.x * 128;
    const int bcol = blockIdx.y;
    const int b    = bcol >> 2, t0 = (bcol & 3) * 128;
    const int dir  = blockIdx.z;
    const int gate = blockIdx.x >> 2;
    const int CPK = CIN >> 6, NCH = CPK * 2;       // 64-k chunks

    const uint32_t sbase = smem_u32(dsm);
    const int rst = dir ? -row_stride : row_stride;
    const __half* Xbase = dir
        ? X + (size_t)b * b_stride + (size_t)(T_DIM + 1) * row_stride
        : X + (size_t)b * b_stride;
    // chunk base row offset: dir0: (t0+kk)*row_stride from Xbase; dir1: -(t0+kk)*row_stride

    float acc[4][8][4];
    #pragma unroll
    for (int i = 0; i < 4; i++)
        #pragma unroll
        for (int j = 0; j < 8; j++)
            #pragma unroll
            for (int k = 0; k < 4; k++) acc[i][j][k] = 0.f;

    // --- precomputed loader offsets: 8 granule-pairs per thread (chunk-invariant)
    uint32_t goff[8];
    int gao[8], gbo[8];
    #pragma unroll
    for (int p = 0; p < 8; p++) {
        int gid = p * 128 + tid;                   // 0..1023
        int r = gid >> 3, g = gid & 7;
        goff[p] = (uint32_t)r * 128 + (uint32_t)((g ^ (r & 7)) << 4);
        gao[p]  = r * CIN + g * 8;
        gbo[p]  = r * rst + g * 8;
    }

    auto issue = [&](int ic, int s) {
        const int kk = (ic >= CPK) ? 1 : 0;
        const int c0 = (kk ? ic - CPK : ic) << 6;
        const __half* Ab = Wt + (size_t)((dir * 2 + kk) * 2048 + m0) * CIN + c0;
        const __half* Bb = Xbase + (ptrdiff_t)(t0 + kk) * rst + c0;
        const uint32_t st = sbase + s * 32768;
        #pragma unroll
        for (int p = 0; p < 8; p++) {
            cpa16(st + goff[p],         Ab + gao[p]);
            cpa16(st + 16384 + goff[p], Bb + gbo[p]);
        }
    };

    issue(0, 0); CP_COMMIT();
    issue(1, 1); CP_COMMIT();

    // --- fragment offsets (ks=0); per-ks address = base ^ (ks<<5)
    const int lq = lane >> 3, lr = lane & 7;
    uint32_t aoff[4], boff[4];
    #pragma unroll
    for (int mf = 0; mf < 4; mf++) {
        int R = mo + mf * 16 + lr + ((lq & 1) << 3);
        int q = lq >> 1;
        aoff[mf] = (uint32_t)R * 128 + (uint32_t)((q ^ (R & 7)) << 4);
    }
    #pragma unroll
    for (int nb = 0; nb < 4; nb++) {
        int R = no + nb * 16 + lr + ((lq >> 1) << 3);
        int q = lq & 1;
        boff[nb] = 16384u + (uint32_t)R * 128 + (uint32_t)((q ^ (R & 7)) << 4);
    }

    for (int ic = 0; ic < NCH; ic++) {
        const int s = ic % 3;
        CP_WAIT1();
        __syncthreads();

        const uint32_t St = sbase + s * 32768;
        #pragma unroll
        for (int ks = 0; ks < 4; ks++) {
            const uint32_t kx = (uint32_t)ks << 5;
            uint32_t a[4][4];
            #pragma unroll
            for (int mf = 0; mf < 4; mf++)
                ldm_x4(a[mf], (St + aoff[mf]) ^ kx);
            uint32_t bf[4][4];
            #pragma unroll
            for (int nb = 0; nb < 4; nb++)
                ldm_x4(bf[nb], (St + boff[nb]) ^ kx);
            #pragma unroll
            for (int mf = 0; mf < 4; mf++)
                #pragma unroll
                for (int nf = 0; nf < 8; nf++)
                    mma_f16(acc[mf][nf], a[mf], bf[nf >> 1][(nf & 1) * 2], bf[nf >> 1][(nf & 1) * 2 + 1]);
        }

        const int nx = ic + 2;
        if (nx < NCH) issue(nx, nx % 3);
        CP_COMMIT();
    }

    // --- epilogue: bias + activation, direct stores
    const float* bb = bias + dir * 2048 + m0;
    __half* Gbase = G + ((size_t)(dir * B_DIM + b) * T_DIM + t0) * M_DIM + m0;
    #pragma unroll
    for (int mf = 0; mf < 4; mf++) {
        const int mr = mo + mf * 16 + lm;
        const float blo = bb[mr], bhi = bb[mr + 8];
        #pragma unroll
        for (int nf = 0; nf < 8; nf++) {
            const int t = no + nf * 8 + 2 * lk;
            __half* p = Gbase + (size_t)t * M_DIM + mr;
            float v0 = acc[mf][nf][0] + blo;
            float v1 = acc[mf][nf][1] + blo;
            float v2 = acc[mf][nf][2] + bhi;
            float v3 = acc[mf][nf][3] + bhi;
            if (gate == 0) {
                v0 = 2.f * sigm(2.f * v0) - 1.f;  v1 = 2.f * sigm(2.f * v1) - 1.f;
                v2 = 2.f * sigm(2.f * v2) - 1.f;  v3 = 2.f * sigm(2.f * v3) - 1.f;
            } else {
                v0 = sigm(v0); v1 = sigm(v1); v2 = sigm(v2); v3 = sigm(v3);
            }
            p[0] = __float2half_rn(v0);  p[M_DIM]     = __float2half_rn(v1);
            p[8] = __float2half_rn(v2);  p[M_DIM + 8] = __float2half_rn(v3);
        }
    }
}

// ---------------------------------------------------------------------------
// Chunk-parallel scan (3 phases) — unchanged
// ---------------------------------------------------------------------------
__global__ void scan_a(const __half* __restrict__ G,
                       float* __restrict__ sA, float* __restrict__ sB)
{
    const int h = blockIdx.x * 128 + threadIdx.x;
    const int b = blockIdx.y;
    const int dir = blockIdx.z >> 3, ch = blockIdx.z & 7;
    const __half* Gd = G + ((size_t)(dir * B_DIM + b) * T_DIM + ch * CHK) * M_DIM + h;

    float a = 1.f, c = 0.f;
    #pragma unroll 4
    for (int t = 0; t < CHK; t++) {
        const __half* p = Gd + (size_t)t * M_DIM;
        float z = __half2float(p[0]);
        float f = __half2float(p[512]);
        float i = __half2float(p[1536]);
        a *= f;
        c = fmaf(f, c, i * z);
    }
    int o = (((dir * B_DIM + b) * NCHK) + ch) * 512 + h;
    sA[o] = a; sB[o] = c;
}

__global__ void scan_b(const float* __restrict__ sA, const float* __restrict__ sB,
                       float* __restrict__ cs)
{
    int idx = blockIdx.x * 256 + threadIdx.x;
    int lane = idx >> 9, h = idx & 511;
    float c = 0.f;
    #pragma unroll
    for (int j = 0; j < NCHK; j++) {
        int o = (lane * NCHK + j) * 512 + h;
        cs[o] = c;
        c = fmaf(sA[o], c, sB[o]);
    }
}

__global__ void scan_c(const __half* __restrict__ G, const float* __restrict__ cs,
                       float* __restrict__ o1f, __half* __restrict__ o1h,
                       float* __restrict__ hn, int mode)
{
    const int h = blockIdx.x * 128 + threadIdx.x;
    const int b = blockIdx.y;
    const int dir = blockIdx.z >> 3, ch = blockIdx.z & 7;
    const __half* Gd = G + ((size_t)(dir * B_DIM + b) * T_DIM + ch * CHK) * M_DIM + h;
    const int co = dir * 512 + h;

    float c = cs[(((dir * B_DIM + b) * NCHK) + ch) * 512 + h];
    #pragma unroll 4
    for (int t = 0; t < CHK; t++) {
        const __half* p = Gd + (size_t)t * M_DIM;
        float z  = __half2float(p[0]);
        float f  = __half2float(p[512]);
        float og = __half2float(p[1024]);
        float i  = __half2float(p[1536]);
        c = fmaf(f, c, i * z);
        float val = og * c;
        int gt = ch * CHK + t;
        if (mode == 0) {
            o1h[((size_t)b * (T_DIM + 2) + 1 + gt) * 1024 + co] = __float2half_rn(val);
        } else {
            o1f[((size_t)gt * B_DIM + b) * 1024 + co] = val;
        }
        if ((dir == 0 && gt == T_DIM - 2) || (dir == 1 && gt == 0))
            hn[(size_t)b * 1024 + co] = val;
    }
}

// ---------------------------------------------------------------------------
extern "C" void kernel_launch(void* const* d_in, const int* in_sizes, int n_in,
                              void* d_out, int out_size)
{
    const float* x  = (const float*)d_in[0];
    const float* w0 = (const float*)d_in[1];
    const float* b0 = (const float*)d_in[2];
    const float* w1 = (const float*)d_in[3];
    const float* b1 = (const float*)d_in[4];
    float* out = (float*)d_out;

    __half *gates, *xp, *h1p, *wt1, *wt2;
    float *sA, *sB, *cst;
    cudaGetSymbolAddress((void**)&gates, g_gates);
    cudaGetSymbolAddress((void**)&xp,  g_xp);
    cudaGetSymbolAddress((void**)&h1p, g_h1p);
    cudaGetSymbolAddress((void**)&wt1, g_wt1);
    cudaGetSymbolAddress((void**)&wt2, g_wt2);
    cudaGetSymbolAddress((void**)&sA,  g_sumA);
    cudaGetSymbolAddress((void**)&sB,  g_sumB);
    cudaGetSymbolAddress((void**)&cst, g_cst);

    cudaFuncSetAttribute(qrnn_gemm_mma, cudaFuncAttributeMaxDynamicSharedMemorySize, 96 * 1024);

    const size_t OUT_SEQ = (size_t)T_DIM * B_DIM * 2 * H_DIM;
    const size_t HN_L    = (size_t)B_DIM * 2 * H_DIM;

    // 3 prep launches, then the GEMM is launch #4 (ncu's profiled slot)
    prep_w<<<(2 * 2 * 2048 * C1) / 256, 256>>>(w0, wt1, C1, h1p);
    prep_w<<<(2 * 2 * 2048 * 2 * H_DIM) / 256, 256>>>(w1, wt2, 2 * H_DIM, nullptr);
    prep_x<<<(T_DIM * BC) / 256, 256>>>(x, xp);

    dim3 ggrid(16, 128, 2), gblk(128);
    dim3 scgrid(4, B_DIM, 16), scblk(128);
    const int DSM = 96 * 1024;

    // Layer 1: xp (row, b, c): row_stride = BC, b_stride = C1
    qrnn_gemm_mma<<<ggrid, gblk, DSM>>>(xp, wt1, b0, gates, C1, BC, C1);
    scan_a<<<scgrid, scblk>>>(gates, sA, sB);
    scan_b<<<128, 256>>>(sA, sB, cst);
    scan_c<<<scgrid, scblk>>>(gates, cst, nullptr, h1p, out + OUT_SEQ, 0);

    // Layer 2: h1p (b, row, c): row_stride = 1024, b_stride = 514*1024
    qrnn_gemm_mma<<<ggrid, gblk, DSM>>>(h1p, wt2, b1, gates, 2 * H_DIM,
                                        1024, (T_DIM + 2) * 1024);
    scan_a<<<scgrid, scblk>>>(gates, sA, sB);
    scan_b<<<128, 256>>>(sA, sB, cst);
    scan_c<<<scgrid, scblk>>>(gates, cst, out, nullptr, out + OUT_SEQ + HN_L, 1);
}

// round 14
// speedup vs baseline: 1.7806x; 1.0263x over previous
#include <cuda_runtime.h>
#include <cuda_fp16.h>
#include <cstdint>
#include <math.h>

#define T_DIM 512
#define B_DIM 32
#define C1    512
#define H_DIM 512
#define M_DIM 2048          // 4 gates * H per direction
#define BC    (B_DIM * C1)  // 16384
#define NCHK  8
#define CHK   64            // T / NCHK

// ---------------------------------------------------------------------------
// Scratch (__device__ globals — no runtime allocation)
// ---------------------------------------------------------------------------
__device__ __align__(1024) __half g_gates[2ull * B_DIM * T_DIM * M_DIM];      // activated gates fp16
__device__ __align__(1024) __half g_xp[(size_t)(T_DIM + 2) * BC];             // padded x: rows 0..513
__device__ __align__(1024) __half g_h1p[(size_t)B_DIM * (T_DIM + 2) * 1024];  // layer-1 out, same padding
__device__ __align__(1024) __half g_wt1[2ull * 2 * M_DIM * C1];               // Wt[dir][kk][m][c]
__device__ __align__(1024) __half g_wt2[2ull * 2 * M_DIM * 2 * H_DIM];
__device__ float g_sumA[2 * B_DIM * NCHK * 512];
__device__ float g_sumB[2 * B_DIM * NCHK * 512];
__device__ float g_cst [2 * B_DIM * NCHK * 512];

// ---------------------------------------------------------------------------
__device__ __forceinline__ uint32_t smem_u32(const void* p) {
    uint32_t a;
    asm("{ .reg .u64 t; cvta.to.shared.u64 t, %1; cvt.u32.u64 %0, t; }" : "=r"(a) : "l"(p));
    return a;
}
__device__ __forceinline__ void cpa16(uint32_t dst, const void* src) {
    asm volatile("cp.async.cg.shared.global [%0], [%1], 16;" :: "r"(dst), "l"(src));
}
#define CP_COMMIT() asm volatile("cp.async.commit_group;" ::: "memory")
#define CP_WAIT1()  asm volatile("cp.async.wait_group 1;" ::: "memory")

__device__ __forceinline__ void ldm_x4(uint32_t r[4], uint32_t addr) {
    asm volatile("ldmatrix.sync.aligned.m8n8.x4.shared.b16 {%0,%1,%2,%3}, [%4];"
                 : "=r"(r[0]), "=r"(r[1]), "=r"(r[2]), "=r"(r[3]) : "r"(addr));
}
__device__ __forceinline__ void mma_f16(float c[4], const uint32_t a[4], uint32_t b0, uint32_t b1) {
    asm volatile("mma.sync.aligned.m16n8k16.row.col.f32.f16.f16.f32 "
                 "{%0,%1,%2,%3}, {%4,%5,%6,%7}, {%8,%9}, {%0,%1,%2,%3};"
                 : "+f"(c[0]), "+f"(c[1]), "+f"(c[2]), "+f"(c[3])
                 : "r"(a[0]), "r"(a[1]), "r"(a[2]), "r"(a[3]), "r"(b0), "r"(b1));
}
__device__ __forceinline__ float sigm(float v) { return 1.f / (1.f + __expf(-v)); }

// ---------------------------------------------------------------------------
// Prepasses
// ---------------------------------------------------------------------------
__global__ void prep_w(const float* __restrict__ W, __half* __restrict__ Wt, int CIN,
                       __half* __restrict__ h1p_pads)
{
    int o = blockIdx.x * 256 + threadIdx.x;
    int c   = o % CIN;
    int m   = (o / CIN) & 2047;
    int kk  = (o / (CIN * 2048)) & 1;
    int dir = o / (CIN * 4096);
    int g = m >> 9, h = m & 511;
    Wt[o] = __float2half_rn(W[(((size_t)(dir * 4 + g) * 512 + h) * CIN + c) * 2 + kk]);
    if (h1p_pads && o < 32768) {
        __half z = __float2half_rn(0.f);
        int b = o >> 10, cc = o & 1023;
        h1p_pads[(size_t)b * (T_DIM + 2) * 1024 + cc] = z;
        h1p_pads[((size_t)b * (T_DIM + 2) + T_DIM + 1) * 1024 + cc] = z;
    }
}

__global__ void prep_x(const float* __restrict__ x, __half* __restrict__ Xp)
{
    int idx = blockIdx.x * 256 + threadIdx.x;
    int r = idx & (BC - 1);
    int t = idx >> 14;
    Xp[(size_t)(t + 1) * BC + r] = __float2half_rn(x[idx]);
    if (t == 0) {
        __half z = __float2half_rn(0.f);
        Xp[r] = z;
        Xp[(size_t)(T_DIM + 1) * BC + r] = z;
    }
}

// ---------------------------------------------------------------------------
// fp16 mma.sync m16n8k16 GEMM. CTA 128m x 128t, 8 warps 32x64, 2 CTA/SM.
// K-chunk = 64 (stage A[128x64] 16KB + B[128x64] 16KB = 32KB; 3 stages 96KB).
// Swizzle: 128B rows of 8 granules, g ^= (r&7). ldmatrix addr(ks) = addr0 ^ (ks<<5).
// Loader: chunk-invariant per-thread offsets + scalar running chunk offsets
// (one 64-bit add per cp.async). Next chunk issued right after the barrier.
// dir=1 reads the padded buffer with negative row stride.
// ---------------------------------------------------------------------------
__global__ __launch_bounds__(256, 2)
void qrnn_gemm_mma(const __half* __restrict__ X,
                   const __half* __restrict__ Wt, const float* __restrict__ bias,
                   __half* __restrict__ G, int CIN, int row_stride, int b_stride)
{
    extern __shared__ __align__(128) char dsm[];   // 3 stages * 32 KB
    const int tid  = threadIdx.x;
    const int wid  = tid >> 5, lane = tid & 31;
    const int lm   = lane >> 2, lk = lane & 3;
    const int mo   = (wid & 3) * 32;               // 4 m-warps
    const int no   = (wid >> 2) * 64;              // 2 t-warps
    const int m0   = blockIdx.x * 128;
    const int bcol = blockIdx.y;
    const int b    = bcol >> 2, t0 = (bcol & 3) * 128;
    const int dir  = blockIdx.z;
    const int gate = blockIdx.x >> 2;
    const int CPK = CIN >> 6, NCH = CPK * 2;       // 64-k chunks

    const uint32_t sbase = smem_u32(dsm);
    const int rst = dir ? -row_stride : row_stride;
    const __half* Xbase = dir
        ? X + (size_t)b * b_stride + (size_t)(T_DIM + 1) * row_stride
        : X + (size_t)b * b_stride;

    float acc[2][8][4];
    #pragma unroll
    for (int i = 0; i < 2; i++)
        #pragma unroll
        for (int j = 0; j < 8; j++)
            #pragma unroll
            for (int k = 0; k < 4; k++) acc[i][j][k] = 0.f;

    // --- loader: per-thread chunk-invariant offsets (4 granule-pairs)
    uint32_t goff[4];
    int gao[4], gbo[4];
    #pragma unroll
    for (int p = 0; p < 4; p++) {
        int gid = p * 256 + tid;                   // 0..1023
        int r = gid >> 3, g = gid & 7;
        goff[p] = (uint32_t)r * 128 + (uint32_t)((g ^ (r & 7)) << 4);
        gao[p]  = r * CIN + g * 8;
        gbo[p]  = r * rst + g * 8;
    }
    const __half* Ab0 = Wt + (size_t)((dir * 2) * 2048 + m0) * CIN;
    const __half* Bb0 = Xbase + (ptrdiff_t)t0 * rst;
    ptrdiff_t offA = 0, offB = 0;                  // = kk*(2048*CIN or rst) + c0
    const ptrdiff_t dA_kk = (ptrdiff_t)2048 * CIN - (ptrdiff_t)(CPK - 1) * 64;
    const ptrdiff_t dB_kk = (ptrdiff_t)rst - (ptrdiff_t)(CPK - 1) * 64;
    int iss = 0;

    auto issue = [&](int s) {
        const uint32_t st = sbase + s * 32768;
        #pragma unroll
        for (int p = 0; p < 4; p++) {
            cpa16(st + goff[p],         Ab0 + offA + gao[p]);
            cpa16(st + 16384 + goff[p], Bb0 + offB + gbo[p]);
        }
        if (iss == CPK - 1) { offA += dA_kk; offB += dB_kk; }
        else                { offA += 64;    offB += 64;    }
        iss++;
    };

    issue(0); CP_COMMIT();
    issue(1); CP_COMMIT();

    // --- fragment offsets (ks=0); per-ks address = base ^ (ks<<5)
    const int lq = lane >> 3, lr = lane & 7;
    uint32_t aoff[2], boff[4];
    #pragma unroll
    for (int mf = 0; mf < 2; mf++) {
        int R = mo + mf * 16 + lr + ((lq & 1) << 3);
        int q = lq >> 1;
        aoff[mf] = (uint32_t)R * 128 + (uint32_t)((q ^ (R & 7)) << 4);
    }
    #pragma unroll
    for (int nb = 0; nb < 4; nb++) {
        int R = no + nb * 16 + lr + ((lq >> 1) << 3);
        int q = lq & 1;
        boff[nb] = 16384u + (uint32_t)R * 128 + (uint32_t)((q ^ (R & 7)) << 4);
    }

    for (int ic = 0; ic < NCH; ic++) {
        const int s = ic % 3;
        CP_WAIT1();
        __syncthreads();

        // issue next chunk NOW: loads overlap this chunk's full compute phase
        if (ic + 2 < NCH) { issue((ic + 2) % 3); CP_COMMIT(); }

        const uint32_t St = sbase + s * 32768;
        #pragma unroll
        for (int ks = 0; ks < 4; ks++) {
            const uint32_t kx = (uint32_t)ks << 5;
            uint32_t a[2][4];
            #pragma unroll
            for (int mf = 0; mf < 2; mf++)
                ldm_x4(a[mf], (St + aoff[mf]) ^ kx);
            uint32_t bf[4][4];
            #pragma unroll
            for (int nb = 0; nb < 4; nb++)
                ldm_x4(bf[nb], (St + boff[nb]) ^ kx);
            #pragma unroll
            for (int mf = 0; mf < 2; mf++)
                #pragma unroll
                for (int nf = 0; nf < 8; nf++)
                    mma_f16(acc[mf][nf], a[mf], bf[nf >> 1][(nf & 1) * 2], bf[nf >> 1][(nf & 1) * 2 + 1]);
        }
    }

    // --- epilogue: bias + activation, direct stores
    const float* bb = bias + dir * 2048 + m0;
    __half* Gbase = G + ((size_t)(dir * B_DIM + b) * T_DIM + t0) * M_DIM + m0;
    #pragma unroll
    for (int mf = 0; mf < 2; mf++) {
        const int mr = mo + mf * 16 + lm;
        const float blo = bb[mr], bhi = bb[mr + 8];
        #pragma unroll
        for (int nf = 0; nf < 8; nf++) {
            const int t = no + nf * 8 + 2 * lk;
            __half* p = Gbase + (size_t)t * M_DIM + mr;
            float v0 = acc[mf][nf][0] + blo;
            float v1 = acc[mf][nf][1] + blo;
            float v2 = acc[mf][nf][2] + bhi;
            float v3 = acc[mf][nf][3] + bhi;
            if (gate == 0) {
                v0 = 2.f * sigm(2.f * v0) - 1.f;  v1 = 2.f * sigm(2.f * v1) - 1.f;
                v2 = 2.f * sigm(2.f * v2) - 1.f;  v3 = 2.f * sigm(2.f * v3) - 1.f;
            } else {
                v0 = sigm(v0); v1 = sigm(v1); v2 = sigm(v2); v3 = sigm(v3);
            }
            p[0] = __float2half_rn(v0);  p[M_DIM]     = __float2half_rn(v1);
            p[8] = __float2half_rn(v2);  p[M_DIM + 8] = __float2half_rn(v3);
        }
    }
}

// ---------------------------------------------------------------------------
// Chunk-parallel scan (3 phases) — unchanged
// ---------------------------------------------------------------------------
__global__ void scan_a(const __half* __restrict__ G,
                       float* __restrict__ sA, float* __restrict__ sB)
{
    const int h = blockIdx.x * 128 + threadIdx.x;
    const int b = blockIdx.y;
    const int dir = blockIdx.z >> 3, ch = blockIdx.z & 7;
    const __half* Gd = G + ((size_t)(dir * B_DIM + b) * T_DIM + ch * CHK) * M_DIM + h;

    float a = 1.f, c = 0.f;
    #pragma unroll 4
    for (int t = 0; t < CHK; t++) {
        const __half* p = Gd + (size_t)t * M_DIM;
        float z = __half2float(p[0]);
        float f = __half2float(p[512]);
        float i = __half2float(p[1536]);
        a *= f;
        c = fmaf(f, c, i * z);
    }
    int o = (((dir * B_DIM + b) * NCHK) + ch) * 512 + h;
    sA[o] = a; sB[o] = c;
}

__global__ void scan_b(const float* __restrict__ sA, const float* __restrict__ sB,
                       float* __restrict__ cs)
{
    int idx = blockIdx.x * 256 + threadIdx.x;
    int lane = idx >> 9, h = idx & 511;
    float c = 0.f;
    #pragma unroll
    for (int j = 0; j < NCHK; j++) {
        int o = (lane * NCHK + j) * 512 + h;
        cs[o] = c;
        c = fmaf(sA[o], c, sB[o]);
    }
}

__global__ void scan_c(const __half* __restrict__ G, const float* __restrict__ cs,
                       float* __restrict__ o1f, __half* __restrict__ o1h,
                       float* __restrict__ hn, int mode)
{
    const int h = blockIdx.x * 128 + threadIdx.x;
    const int b = blockIdx.y;
    const int dir = blockIdx.z >> 3, ch = blockIdx.z & 7;
    const __half* Gd = G + ((size_t)(dir * B_DIM + b) * T_DIM + ch * CHK) * M_DIM + h;
    const int co = dir * 512 + h;

    float c = cs[(((dir * B_DIM + b) * NCHK) + ch) * 512 + h];
    #pragma unroll 4
    for (int t = 0; t < CHK; t++) {
        const __half* p = Gd + (size_t)t * M_DIM;
        float z  = __half2float(p[0]);
        float f  = __half2float(p[512]);
        float og = __half2float(p[1024]);
        float i  = __half2float(p[1536]);
        c = fmaf(f, c, i * z);
        float val = og * c;
        int gt = ch * CHK + t;
        if (mode == 0) {
            o1h[((size_t)b * (T_DIM + 2) + 1 + gt) * 1024 + co] = __float2half_rn(val);
        } else {
            o1f[((size_t)gt * B_DIM + b) * 1024 + co] = val;
        }
        if ((dir == 0 && gt == T_DIM - 2) || (dir == 1 && gt == 0))
            hn[(size_t)b * 1024 + co] = val;
    }
}

// ---------------------------------------------------------------------------
extern "C" void kernel_launch(void* const* d_in, const int* in_sizes, int n_in,
                              void* d_out, int out_size)
{
    const float* x  = (const float*)d_in[0];
    const float* w0 = (const float*)d_in[1];
    const float* b0 = (const float*)d_in[2];
    const float* w1 = (const float*)d_in[3];
    const float* b1 = (const float*)d_in[4];
    float* out = (float*)d_out;

    __half *gates, *xp, *h1p, *wt1, *wt2;
    float *sA, *sB, *cst;
    cudaGetSymbolAddress((void**)&gates, g_gates);
    cudaGetSymbolAddress((void**)&xp,  g_xp);
    cudaGetSymbolAddress((void**)&h1p, g_h1p);
    cudaGetSymbolAddress((void**)&wt1, g_wt1);
    cudaGetSymbolAddress((void**)&wt2, g_wt2);
    cudaGetSymbolAddress((void**)&sA,  g_sumA);
    cudaGetSymbolAddress((void**)&sB,  g_sumB);
    cudaGetSymbolAddress((void**)&cst, g_cst);

    cudaFuncSetAttribute(qrnn_gemm_mma, cudaFuncAttributeMaxDynamicSharedMemorySize, 96 * 1024);

    const size_t OUT_SEQ = (size_t)T_DIM * B_DIM * 2 * H_DIM;
    const size_t HN_L    = (size_t)B_DIM * 2 * H_DIM;

    // 3 prep launches, then the GEMM is launch #4 (ncu's profiled slot)
    prep_w<<<(2 * 2 * 2048 * C1) / 256, 256>>>(w0, wt1, C1, h1p);
    prep_w<<<(2 * 2 * 2048 * 2 * H_DIM) / 256, 256>>>(w1, wt2, 2 * H_DIM, nullptr);
    prep_x<<<(T_DIM * BC) / 256, 256>>>(x, xp);

    dim3 ggrid(16, 128, 2), gblk(256);
    dim3 scgrid(4, B_DIM, 16), scblk(128);
    const int DSM = 96 * 1024;

    // Layer 1: xp (row, b, c): row_stride = BC, b_stride = C1
    qrnn_gemm_mma<<<ggrid, gblk, DSM>>>(xp, wt1, b0, gates, C1, BC, C1);
    scan_a<<<scgrid, scblk>>>(gates, sA, sB);
    scan_b<<<128, 256>>>(sA, sB, cst);
    scan_c<<<scgrid, scblk>>>(gates, cst, nullptr, h1p, out + OUT_SEQ, 0);

    // Layer 2: h1p (b, row, c): row_stride = 1024, b_stride = 514*1024
    qrnn_gemm_mma<<<ggrid, gblk, DSM>>>(h1p, wt2, b1, gates, 2 * H_DIM,
                                        1024, (T_DIM + 2) * 1024);
    scan_a<<<scgrid, scblk>>>(gates, sA, sB);
    scan_b<<<128, 256>>>(sA, sB, cst);
    scan_c<<<scgrid, scblk>>>(gates, cst, out, nullptr, out + OUT_SEQ + HN_L, 1);
}